// round 7
// baseline (speedup 1.0000x reference)
#include <cuda_runtime.h>
#include <cuda_fp16.h>
#include <math.h>

#define BB   2
#define CC   64
#define NPTS 20000
#define KK   16
#define CO   64
#define NODES (BB * NPTS)

// Scratch (device globals: allocation-free rule)
// U/V stored as fp16 rows of 64 halves per node (halves gather traffic).
__device__ uint4 g_U[NODES * 8];      // (W1-W2) @ x   per node, fp16
__device__ uint4 g_V[NODES * 8];      // W2      @ x   per node, fp16
__device__ float g_posT[NODES * 4];   // pos transposed to [node][4]

__device__ __forceinline__ unsigned f2h2(float lo, float hi) {
    __half2 h = __floats2half2_rn(lo, hi);
    return *reinterpret_cast<unsigned*>(&h);
}

// ---------------------------------------------------------------------------
// Kernel 1: per-node transform u = (W1-W2)x, v = W2 x, fused pos transpose
// AND fused weight prep (no separate wprep launch).
//
// sW logical layout [c][o] with XOR swizzle: element (c,o) lives at
//   sW[c*128 + (o ^ sw(c))],  sw(c) = ((c>>2)&7) << 2
// Staging reads W coalesced (lanes = consecutive c2) and stores scattered
// (4-way bank conflict instead of 32-way thanks to the swizzle). Pass 2
// folds W1-W2 in smem. Compute loop fully unrolled so swizzled offsets are
// compile-time immediates; all-lane LDS broadcasts remain conflict-free.
//
// Thread (og = tid>>5, ng = tid&31) computes outputs [og*16, og*16+16) for
// nodes base+2*ng, base+2*ng+1. Scalar FMA (fma-pipe floor).
// ---------------------------------------------------------------------------
__global__ __launch_bounds__(256) void uv_kernel(const float* __restrict__ x,
                                                 const float* __restrict__ pos,
                                                 const float* __restrict__ W) {
    __shared__ float sW[64 * 128];   // 32 KB (swizzled)
    __shared__ float sx[64 * 64];    // 16 KB

    int tid  = threadIdx.x;
    int base = blockIdx.x * 64;

    // --- Stage W (pass 1): coalesced float4 reads, swizzled transposed STS.
    {
        const float4* W4 = reinterpret_cast<const float4*>(W);  // 2048 quads
#pragma unroll
        for (int j = 0; j < 8; ++j) {
            int i4 = tid + j * 256;
            int o  = i4 >> 5;          // output row 0..63
            int c4 = i4 & 31;          // quad within the 128-wide input dim
            float4 w = W4[i4];
#pragma unroll
            for (int m = 0; m < 4; ++m) {
                int   c2  = c4 * 4 + m;          // 0..127
                float val = (&w.x)[m];
                int   c   = c2 & 63;
                int   oc  = (c2 < 64) ? o : (64 + o);
                int   sw  = ((c >> 2) & 7) << 2;
                sW[c * 128 + (oc ^ sw)] = val;   // (64+o)^sw == 64 + (o^sw)
            }
        }
    }

    // --- Stage x tile: sx[c][nl] = x[b, c, n] (coalesced over nl).
#pragma unroll
    for (int j = 0; j < 16; ++j) {
        int i  = tid + j * 256;
        int c  = i >> 6, nl = i & 63;
        int node = base + nl;
        int b  = node / NPTS;
        int n  = node - b * NPTS;
        sx[c * 64 + nl] = x[b * CC * NPTS + c * NPTS + n];
    }

    // --- pos transpose by the first 64 threads.
    if (tid < 64) {
        int node = base + tid;
        int b = node / NPTS;
        int n = node - b * NPTS;
        const float* pb = pos + b * 3 * NPTS + n;
        float4 p;
        p.x = pb[0];
        p.y = pb[NPTS];
        p.z = pb[2 * NPTS];
        p.w = 0.0f;
        reinterpret_cast<float4*>(g_posT)[node] = p;
    }
    __syncthreads();

    // --- Pass 2: A -= B elementwise in the swizzled domain (pairing holds
    // because B's swizzled slot is exactly A's slot + 64). Conflict-free.
#pragma unroll
    for (int a = tid; a < 4096; a += 256) {
        int c  = a >> 6;
        int oo = a & 63;
        sW[c * 128 + oo] -= sW[c * 128 + oo + 64];
    }
    __syncthreads();

    int og = tid >> 5;          // output group 0..7 (16 outputs each)
    int ng = tid & 31;          // node pair 0..31

    float a0[16], a1[16];
#pragma unroll
    for (int t = 0; t < 16; ++t) { a0[t] = 0.0f; a1[t] = 0.0f; }

    const float2* xcol = reinterpret_cast<const float2*>(sx) + ng;
    const float4* sW4  = reinterpret_cast<const float4*>(sW);
    const float4* pA   = sW4 + og * 4;         // K bit2 clear
    const float4* pB   = sW4 + ((og * 4) ^ 4); // K bit2 set

#pragma unroll
    for (int c = 0; c < 64; ++c) {
        float2 xx = xcol[c * 32];
        const int K  = (c >> 2) & 7;            // compile-time per iteration
        const float4* p = (K & 4) ? pB : pA;
        float4 w0 = p[c * 32 + (0 ^ (K & 3))];
        float4 w1 = p[c * 32 + (1 ^ (K & 3))];
        float4 w2 = p[c * 32 + (2 ^ (K & 3))];
        float4 w3 = p[c * 32 + (3 ^ (K & 3))];
        a0[0]  = fmaf(w0.x, xx.x, a0[0]);   a1[0]  = fmaf(w0.x, xx.y, a1[0]);
        a0[1]  = fmaf(w0.y, xx.x, a0[1]);   a1[1]  = fmaf(w0.y, xx.y, a1[1]);
        a0[2]  = fmaf(w0.z, xx.x, a0[2]);   a1[2]  = fmaf(w0.z, xx.y, a1[2]);
        a0[3]  = fmaf(w0.w, xx.x, a0[3]);   a1[3]  = fmaf(w0.w, xx.y, a1[3]);
        a0[4]  = fmaf(w1.x, xx.x, a0[4]);   a1[4]  = fmaf(w1.x, xx.y, a1[4]);
        a0[5]  = fmaf(w1.y, xx.x, a0[5]);   a1[5]  = fmaf(w1.y, xx.y, a1[5]);
        a0[6]  = fmaf(w1.z, xx.x, a0[6]);   a1[6]  = fmaf(w1.z, xx.y, a1[6]);
        a0[7]  = fmaf(w1.w, xx.x, a0[7]);   a1[7]  = fmaf(w1.w, xx.y, a1[7]);
        a0[8]  = fmaf(w2.x, xx.x, a0[8]);   a1[8]  = fmaf(w2.x, xx.y, a1[8]);
        a0[9]  = fmaf(w2.y, xx.x, a0[9]);   a1[9]  = fmaf(w2.y, xx.y, a1[9]);
        a0[10] = fmaf(w2.z, xx.x, a0[10]);  a1[10] = fmaf(w2.z, xx.y, a1[10]);
        a0[11] = fmaf(w2.w, xx.x, a0[11]);  a1[11] = fmaf(w2.w, xx.y, a1[11]);
        a0[12] = fmaf(w3.x, xx.x, a0[12]);  a1[12] = fmaf(w3.x, xx.y, a1[12]);
        a0[13] = fmaf(w3.y, xx.x, a0[13]);  a1[13] = fmaf(w3.y, xx.y, a1[13]);
        a0[14] = fmaf(w3.z, xx.x, a0[14]);  a1[14] = fmaf(w3.z, xx.y, a1[14]);
        a0[15] = fmaf(w3.w, xx.x, a0[15]);  a1[15] = fmaf(w3.w, xx.y, a1[15]);
    }

    // Convert to fp16 and store. og 0..3 -> U, og 4..7 -> V.
    int node0 = base + 2 * ng;
    uint4* dst = ((og < 4) ? g_U : g_V) + node0 * 8 + (og & 3) * 2;
    dst[0] = make_uint4(f2h2(a0[0],  a0[1]),  f2h2(a0[2],  a0[3]),
                        f2h2(a0[4],  a0[5]),  f2h2(a0[6],  a0[7]));
    dst[1] = make_uint4(f2h2(a0[8],  a0[9]),  f2h2(a0[10], a0[11]),
                        f2h2(a0[12], a0[13]), f2h2(a0[14], a0[15]));
    dst[8] = make_uint4(f2h2(a1[0],  a1[1]),  f2h2(a1[2],  a1[3]),
                        f2h2(a1[4],  a1[5]),  f2h2(a1[6],  a1[7]));
    dst[9] = make_uint4(f2h2(a1[8],  a1[9]),  f2h2(a1[10], a1[11]),
                        f2h2(a1[12], a1[13]), f2h2(a1[14], a1[15]));
}

// ---------------------------------------------------------------------------
// Kernel 2: per-edge combine + suppression + max over K.
// No SHFLs: lanes 0..15 compute suppression into shared (per-warp region,
// __syncwarp only); indices re-read via uniform loads (L1-hit — prologue
// touched the lines). Gathers prefetched in chunks of 8 (16 loads in flight).
// ---------------------------------------------------------------------------
__global__ __launch_bounds__(256) void edge_kernel(const int* __restrict__ ei,
                                                   const float* __restrict__ bias,
                                                   float* __restrict__ out) {
    __shared__ float sm[8 * 66];   // output staging
    __shared__ float ss[8 * 16];   // suppression per warp/k

    int tid  = threadIdx.x;
    int warp = tid >> 5;
    int lane = tid & 31;

    int g = blockIdx.x * 8 + warp;   // 20000 % 8 == 0 -> block never crosses batch
    int b = g / NPTS;
    int n = g - b * NPTS;

    const int* e0 = ei + (b * NPTS + n) * KK;                    // neighbor idx
    const int* e1 = ei + (BB * NPTS * KK) + (b * NPTS + n) * KK; // center idx

    const __half2* Ub = reinterpret_cast<const __half2*>(g_U) + b * NPTS * 32;
    const __half2* Vb = reinterpret_cast<const __half2*>(g_V) + b * NPTS * 32;
    const float4*  Pb = reinterpret_cast<const float4*>(g_posT) + b * NPTS;

    if (lane < KK) {
        int i0 = e0[lane];
        int i1 = e1[lane];
        float4 p1 = Pb[i1];
        float4 p0 = Pb[i0];
        float dx = p1.x - p0.x, dy = p1.y - p0.y, dz = p1.z - p0.z;
        float dis = sqrtf(dx * dx + dy * dy + dz * dz);
        ss[warp * 16 + lane] = 2.0f / (1.0f + __expf(dis));   // 2*sigmoid(-dis)
    }
    __syncwarp();

    float2 bb = reinterpret_cast<const float2*>(bias)[lane];

    float m0 = 0.0f, m1 = 0.0f;

#pragma unroll
    for (int k0 = 0; k0 < KK; k0 += 8) {
        int i1r[8], i0r[8];
#pragma unroll
        for (int j = 0; j < 8; ++j) {
            i1r[j] = __ldg(e1 + k0 + j);   // uniform, L1-hit
            i0r[j] = __ldg(e0 + k0 + j);
        }
        __half2 u[8], v[8];
#pragma unroll
        for (int j = 0; j < 8; ++j) {
            u[j] = Ub[i1r[j] * 32 + lane];
            v[j] = Vb[i0r[j] * 32 + lane];
        }
#pragma unroll
        for (int j = 0; j < 8; ++j) {
            float  s  = ss[warp * 16 + k0 + j];   // LDS broadcast
            float2 uf = __half22float2(u[j]);
            float2 vf = __half22float2(v[j]);
            float y0 = fmaxf(uf.x + vf.x + bb.x, 0.0f) * s;
            float y1 = fmaxf(uf.y + vf.y + bb.y, 0.0f) * s;
            m0 = fmaxf(m0, y0);
            m1 = fmaxf(m1, y1);
        }
    }

    reinterpret_cast<float2*>(sm + warp * 66)[lane] = make_float2(m0, m1);
    __syncthreads();

    int base = blockIdx.x * 8;
    int b2 = base / NPTS;
    int n0 = base - b2 * NPTS;
#pragma unroll
    for (int e = tid; e < CO * 8; e += 256) {
        int o  = e >> 3;
        int nn = e & 7;
        out[(b2 * CO + o) * NPTS + n0 + nn] = sm[nn * 66 + o];
    }
}

extern "C" void kernel_launch(void* const* d_in, const int* in_sizes, int n_in,
                              void* d_out, int out_size) {
    const float* x    = (const float*)d_in[0];
    const int*   ei   = (const int*)d_in[1];
    const float* pos  = (const float*)d_in[2];
    const float* W    = (const float*)d_in[3];
    const float* bias = (const float*)d_in[4];
    float* out = (float*)d_out;

    uv_kernel<<<NODES / 64, 256>>>(x, pos, W);
    edge_kernel<<<NODES / 8, 256>>>(ei, bias, out);
}

// round 9
// speedup vs baseline: 1.1650x; 1.1650x over previous
#include <cuda_runtime.h>
#include <cuda_fp16.h>
#include <math.h>

#define BB   2
#define CC   64
#define NPTS 20000
#define KK   16
#define CO   64
#define NODES (BB * NPTS)

// Scratch (device globals: allocation-free rule)
// U/V stored as fp16 rows of 64 halves per node (halves gather traffic).
__device__ uint4 g_U[NODES * 8];      // (W1-W2) @ x   per node, fp16
__device__ uint4 g_V[NODES * 8];      // W2      @ x   per node, fp16
__device__ float g_posT[NODES * 4];   // pos transposed to [node][4]

__device__ __forceinline__ unsigned f2h2(float lo, float hi) {
    __half2 h = __floats2half2_rn(lo, hi);
    return *reinterpret_cast<unsigned*>(&h);
}
__device__ __forceinline__ __half2 u2h(unsigned x) {
    return *reinterpret_cast<__half2*>(&x);
}
__device__ __forceinline__ __half2 hmax2_xor(__half2 a, int m) {
    unsigned o = __shfl_xor_sync(0xFFFFFFFFu, *reinterpret_cast<unsigned*>(&a), m);
    return __hmax2(a, u2h(o));
}

// ---------------------------------------------------------------------------
// Kernel 1: per-node transform u = (W1-W2)x, v = W2 x, fused pos transpose
// AND fused weight prep. (unchanged — fused beat separate wprep)
// ---------------------------------------------------------------------------
__global__ __launch_bounds__(256) void uv_kernel(const float* __restrict__ x,
                                                 const float* __restrict__ pos,
                                                 const float* __restrict__ W) {
    __shared__ float sW[64 * 128];   // 32 KB (swizzled)
    __shared__ float sx[64 * 64];    // 16 KB

    int tid  = threadIdx.x;
    int base = blockIdx.x * 64;

    // --- Stage W (pass 1): coalesced float4 reads, swizzled transposed STS.
    {
        const float4* W4 = reinterpret_cast<const float4*>(W);  // 2048 quads
#pragma unroll
        for (int j = 0; j < 8; ++j) {
            int i4 = tid + j * 256;
            int o  = i4 >> 5;          // output row 0..63
            int c4 = i4 & 31;          // quad within the 128-wide input dim
            float4 w = W4[i4];
#pragma unroll
            for (int m = 0; m < 4; ++m) {
                int   c2  = c4 * 4 + m;          // 0..127
                float val = (&w.x)[m];
                int   c   = c2 & 63;
                int   oc  = (c2 < 64) ? o : (64 + o);
                int   sw  = ((c >> 2) & 7) << 2;
                sW[c * 128 + (oc ^ sw)] = val;
            }
        }
    }

    // --- Stage x tile: sx[c][nl] = x[b, c, n] (coalesced over nl).
#pragma unroll
    for (int j = 0; j < 16; ++j) {
        int i  = tid + j * 256;
        int c  = i >> 6, nl = i & 63;
        int node = base + nl;
        int b  = node / NPTS;
        int n  = node - b * NPTS;
        sx[c * 64 + nl] = x[b * CC * NPTS + c * NPTS + n];
    }

    // --- pos transpose by the first 64 threads.
    if (tid < 64) {
        int node = base + tid;
        int b = node / NPTS;
        int n = node - b * NPTS;
        const float* pb = pos + b * 3 * NPTS + n;
        float4 p;
        p.x = pb[0];
        p.y = pb[NPTS];
        p.z = pb[2 * NPTS];
        p.w = 0.0f;
        reinterpret_cast<float4*>(g_posT)[node] = p;
    }
    __syncthreads();

    // --- Pass 2: A -= B in the swizzled domain (B slot = A slot + 64).
#pragma unroll
    for (int a = tid; a < 4096; a += 256) {
        int c  = a >> 6;
        int oo = a & 63;
        sW[c * 128 + oo] -= sW[c * 128 + oo + 64];
    }
    __syncthreads();

    int og = tid >> 5;          // output group 0..7 (16 outputs each)
    int ng = tid & 31;          // node pair 0..31

    float a0[16], a1[16];
#pragma unroll
    for (int t = 0; t < 16; ++t) { a0[t] = 0.0f; a1[t] = 0.0f; }

    const float2* xcol = reinterpret_cast<const float2*>(sx) + ng;
    const float4* sW4  = reinterpret_cast<const float4*>(sW);
    const float4* pA   = sW4 + og * 4;
    const float4* pB   = sW4 + ((og * 4) ^ 4);

#pragma unroll
    for (int c = 0; c < 64; ++c) {
        float2 xx = xcol[c * 32];
        const int K  = (c >> 2) & 7;
        const float4* p = (K & 4) ? pB : pA;
        float4 w0 = p[c * 32 + (0 ^ (K & 3))];
        float4 w1 = p[c * 32 + (1 ^ (K & 3))];
        float4 w2 = p[c * 32 + (2 ^ (K & 3))];
        float4 w3 = p[c * 32 + (3 ^ (K & 3))];
        a0[0]  = fmaf(w0.x, xx.x, a0[0]);   a1[0]  = fmaf(w0.x, xx.y, a1[0]);
        a0[1]  = fmaf(w0.y, xx.x, a0[1]);   a1[1]  = fmaf(w0.y, xx.y, a1[1]);
        a0[2]  = fmaf(w0.z, xx.x, a0[2]);   a1[2]  = fmaf(w0.z, xx.y, a1[2]);
        a0[3]  = fmaf(w0.w, xx.x, a0[3]);   a1[3]  = fmaf(w0.w, xx.y, a1[3]);
        a0[4]  = fmaf(w1.x, xx.x, a0[4]);   a1[4]  = fmaf(w1.x, xx.y, a1[4]);
        a0[5]  = fmaf(w1.y, xx.x, a0[5]);   a1[5]  = fmaf(w1.y, xx.y, a1[5]);
        a0[6]  = fmaf(w1.z, xx.x, a0[6]);   a1[6]  = fmaf(w1.z, xx.y, a1[6]);
        a0[7]  = fmaf(w1.w, xx.x, a0[7]);   a1[7]  = fmaf(w1.w, xx.y, a1[7]);
        a0[8]  = fmaf(w2.x, xx.x, a0[8]);   a1[8]  = fmaf(w2.x, xx.y, a1[8]);
        a0[9]  = fmaf(w2.y, xx.x, a0[9]);   a1[9]  = fmaf(w2.y, xx.y, a1[9]);
        a0[10] = fmaf(w2.z, xx.x, a0[10]);  a1[10] = fmaf(w2.z, xx.y, a1[10]);
        a0[11] = fmaf(w2.w, xx.x, a0[11]);  a1[11] = fmaf(w2.w, xx.y, a1[11]);
        a0[12] = fmaf(w3.x, xx.x, a0[12]);  a1[12] = fmaf(w3.x, xx.y, a1[12]);
        a0[13] = fmaf(w3.y, xx.x, a0[13]);  a1[13] = fmaf(w3.y, xx.y, a1[13]);
        a0[14] = fmaf(w3.z, xx.x, a0[14]);  a1[14] = fmaf(w3.z, xx.y, a1[14]);
        a0[15] = fmaf(w3.w, xx.x, a0[15]);  a1[15] = fmaf(w3.w, xx.y, a1[15]);
    }

    // Convert to fp16 and store. og 0..3 -> U, og 4..7 -> V.
    int node0 = base + 2 * ng;
    uint4* dst = ((og < 4) ? g_U : g_V) + node0 * 8 + (og & 3) * 2;
    dst[0] = make_uint4(f2h2(a0[0],  a0[1]),  f2h2(a0[2],  a0[3]),
                        f2h2(a0[4],  a0[5]),  f2h2(a0[6],  a0[7]));
    dst[1] = make_uint4(f2h2(a0[8],  a0[9]),  f2h2(a0[10], a0[11]),
                        f2h2(a0[12], a0[13]), f2h2(a0[14], a0[15]));
    dst[8] = make_uint4(f2h2(a1[0],  a1[1]),  f2h2(a1[2],  a1[3]),
                        f2h2(a1[4],  a1[5]),  f2h2(a1[6],  a1[7]));
    dst[9] = make_uint4(f2h2(a1[8],  a1[9]),  f2h2(a1[10], a1[11]),
                        f2h2(a1[12], a1[13]), f2h2(a1[14], a1[15]));
}

// ---------------------------------------------------------------------------
// Kernel 2: per-edge combine + suppression + max over K — vectorized.
// Warp per point. Lane (esub = lane>>3, q = lane&7) loads the q-th uint4
// (8 halves) of edge (p*4+esub)'s U/V row: one LDG.128 covers what 4 LDG.64
// did before, 8-lane groups are fully coalesced. All 8 gathers in flight.
// half2 math (add, +bias, relu, *s, max); max over esub via shfl butterfly.
// ---------------------------------------------------------------------------
__global__ __launch_bounds__(256) void edge_kernel(const int* __restrict__ ei,
                                                   const float* __restrict__ bias,
                                                   float* __restrict__ out) {
    __shared__ float    sm[8 * 66];   // output staging
    __shared__ unsigned ssh[8 * 16];  // suppression as half2(s,s), per warp/k
    __shared__ int      si[8 * 32];   // [warp][0..15: i1 (center), 16..31: i0]
    __shared__ unsigned sbias[32];    // bias as 32 half2

    int tid  = threadIdx.x;
    int warp = tid >> 5;
    int lane = tid & 31;

    if (tid < 32) {
        float2 bf = reinterpret_cast<const float2*>(bias)[tid];
        sbias[tid] = f2h2(bf.x, bf.y);
    }

    int g = blockIdx.x * 8 + warp;   // 20000 % 8 == 0 -> block never crosses batch
    int b = g / NPTS;
    int n = g - b * NPTS;

    const int* e0 = ei + (b * NPTS + n) * KK;                    // neighbor idx
    const int* e1 = ei + (BB * NPTS * KK) + (b * NPTS + n) * KK; // center idx

    const uint4*  Ub = g_U + b * NPTS * 8;
    const uint4*  Vb = g_V + b * NPTS * 8;
    const float4* Pb = reinterpret_cast<const float4*>(g_posT) + b * NPTS;

    if (lane < KK) {
        int i0 = e0[lane];
        int i1 = e1[lane];
        si[warp * 32 + lane]      = i1;
        si[warp * 32 + 16 + lane] = i0;
        float4 p1 = Pb[i1];
        float4 p0 = Pb[i0];
        float dx = p1.x - p0.x, dy = p1.y - p0.y, dz = p1.z - p0.z;
        float dis = sqrtf(dx * dx + dy * dy + dz * dz);
        float s = 2.0f / (1.0f + __expf(dis));   // 2*sigmoid(-dis)
        ssh[warp * 16 + lane] = f2h2(s, s);
    }
    __syncthreads();   // sbias (cross-warp) + si/ssh

    int esub = lane >> 3;    // which of 4 edges this pass
    int q    = lane & 7;     // which 16B quad of the 128B row

    // Issue all gathers up front (8 LDG.128 in flight per lane).
    uint4    u[4], v[4];
    unsigned sh[4];
#pragma unroll
    for (int p = 0; p < 4; ++p) {
        int k  = p * 4 + esub;
        int i1 = si[warp * 32 + k];
        int i0 = si[warp * 32 + 16 + k];
        u[p]  = Ub[i1 * 8 + q];
        v[p]  = Vb[i0 * 8 + q];
        sh[p] = ssh[warp * 16 + k];
    }

    uint4 bq = reinterpret_cast<const uint4*>(sbias)[q];  // bias for outputs 8q..8q+7
    __half2 b0 = u2h(bq.x), b1 = u2h(bq.y), b2 = u2h(bq.z), b3 = u2h(bq.w);

    const __half2 z = __floats2half2_rn(0.0f, 0.0f);
    __half2 a0 = z, a1 = z, a2 = z, a3 = z;   // relu*positive => >= 0

#pragma unroll
    for (int p = 0; p < 4; ++p) {
        __half2 s2 = u2h(sh[p]);
        a0 = __hmax2(a0, __hmul2(__hmax2(__hadd2(__hadd2(u2h(u[p].x), u2h(v[p].x)), b0), z), s2));
        a1 = __hmax2(a1, __hmul2(__hmax2(__hadd2(__hadd2(u2h(u[p].y), u2h(v[p].y)), b1), z), s2));
        a2 = __hmax2(a2, __hmul2(__hmax2(__hadd2(__hadd2(u2h(u[p].z), u2h(v[p].z)), b2), z), s2));
        a3 = __hmax2(a3, __hmul2(__hmax2(__hadd2(__hadd2(u2h(u[p].w), u2h(v[p].w)), b3), z), s2));
    }

    // Max over esub: lanes {q, q+8, q+16, q+24} hold the 4 edge groups.
    a0 = hmax2_xor(a0, 8);  a1 = hmax2_xor(a1, 8);
    a2 = hmax2_xor(a2, 8);  a3 = hmax2_xor(a3, 8);
    a0 = hmax2_xor(a0, 16); a1 = hmax2_xor(a1, 16);
    a2 = hmax2_xor(a2, 16); a3 = hmax2_xor(a3, 16);

    if (esub == 0) {   // lanes 0..7 write outputs 8q..8q+7 (float)
        float2* dst = reinterpret_cast<float2*>(sm + warp * 66 + q * 8);
        dst[0] = __half22float2(a0);
        dst[1] = __half22float2(a1);
        dst[2] = __half22float2(a2);
        dst[3] = __half22float2(a3);
    }
    __syncthreads();

    int base = blockIdx.x * 8;
    int ob = base / NPTS;               // batch of this block's points
    int on = base - ob * NPTS;          // first point index within batch
#pragma unroll
    for (int e = tid; e < CO * 8; e += 256) {
        int o  = e >> 3;
        int nn = e & 7;
        out[(ob * CO + o) * NPTS + on + nn] = sm[nn * 66 + o];
    }
}

extern "C" void kernel_launch(void* const* d_in, const int* in_sizes, int n_in,
                              void* d_out, int out_size) {
    const float* x    = (const float*)d_in[0];
    const int*   ei   = (const int*)d_in[1];
    const float* pos  = (const float*)d_in[2];
    const float* W    = (const float*)d_in[3];
    const float* bias = (const float*)d_in[4];
    float* out = (float*)d_out;

    uv_kernel<<<NODES / 64, 256>>>(x, pos, W);
    edge_kernel<<<NODES / 8, 256>>>(ei, bias, out);
}